// round 1
// baseline (speedup 1.0000x reference)
#include <cuda_runtime.h>
#include <cstdint>

#define Bb 256
#define Tt 1024
#define Vv 128
#define Hh 128

// Scratch (no allocations allowed): symbol per (b,t), and W_ih transposed.
__device__ unsigned char g_symbols[Bb * Tt];
__device__ float g_WihT[127 * Hh];

// ---------------------------------------------------------------------------
// Kernel 1: extract symbol index from one-hot rows. Warp per (b,t) row.
// One-hot value is exactly 1.0f; sum of (index where v>0.5) over lanes = symbol.
// ---------------------------------------------------------------------------
__global__ void sym_kernel(const float* __restrict__ x) {
    int row  = blockIdx.x * 8 + (threadIdx.x >> 5);
    int lane = threadIdx.x & 31;
    float4 v = reinterpret_cast<const float4*>(x + (size_t)row * Vv)[lane];
    int idx = 0;
    if (v.x > 0.5f) idx = lane * 4 + 0;
    if (v.y > 0.5f) idx = lane * 4 + 1;
    if (v.z > 0.5f) idx = lane * 4 + 2;
    if (v.w > 0.5f) idx = lane * 4 + 3;
#pragma unroll
    for (int o = 16; o; o >>= 1) idx += __shfl_xor_sync(0xffffffffu, idx, o);
    if (lane == 0) g_symbols[row] = (unsigned char)idx;
}

// ---------------------------------------------------------------------------
// Kernel 2: transpose W_ih (H=128, V-1=127) -> g_WihT[f*128 + h]
// so the RNN kernel's per-step gather is one coalesced 128B line per warp.
// ---------------------------------------------------------------------------
__global__ void transpose_kernel(const float* __restrict__ W_ih) {
    int f = blockIdx.x;    // 0..126
    int h = threadIdx.x;   // 0..127
    g_WihT[f * Hh + h] = W_ih[h * 127 + f];
}

// Packed dual-lane fp32 FMA (Blackwell f32x2) — 2x FFMA throughput.
#define FMA2(d, a, b, c) \
    asm("fma.rn.f32x2 %0, %1, %2, %3;" : "=l"(d) : "l"(a), "l"(b), "l"(c))

// ---------------------------------------------------------------------------
// Kernel 3: the RNN. One CTA per batch element, 128 threads; thread i owns
// h[i] and keeps W_hh row i in 64 packed-u64 registers. Early exit at the
// first pad symbol (== length[b]). Epilogue writes hidden + softmax head.
// ---------------------------------------------------------------------------
__global__ __launch_bounds__(128, 2) void rnn_kernel(
    const float* __restrict__ W_hh,
    const float* __restrict__ b_ih,
    const float* __restrict__ b_hh,
    const float* __restrict__ W_out,
    const float* __restrict__ b_out,
    float* __restrict__ out)
{
    __shared__ __align__(16) float hb[2][Hh];
    __shared__ __align__(16) unsigned char ssym[Tt];
    __shared__ float red[2][Hh];

    const int b   = blockIdx.x;
    const int tid = threadIdx.x;

    // Stage this row's symbols into shared (1 KB).
    {
        const uint4* src = reinterpret_cast<const uint4*>(g_symbols + (size_t)b * Tt);
        uint4* dst = reinterpret_cast<uint4*>(ssym);
        for (int i = tid; i < Tt / 16; i += 128) dst[i] = src[i];
    }

    // W_hh row tid -> 64 packed f32x2 registers.
    unsigned long long w2[64];
    {
        const ulonglong2* wr = reinterpret_cast<const ulonglong2*>(W_hh + (size_t)tid * Hh);
#pragma unroll
        for (int c = 0; c < 32; c++) {
            ulonglong2 u = wr[c];
            w2[2 * c]     = u.x;
            w2[2 * c + 1] = u.y;
        }
    }

    const float bsum = b_ih[tid] + b_hh[tid];
    hb[0][tid] = 0.0f;
    __syncthreads();

    int   p = 0;
    int   t = 0;
    int   s = ssym[0];
    float pre = (s > 0) ? g_WihT[(s - 1) * Hh + tid] : 0.0f;

    while (s > 0) {
        const ulonglong2* h2 = reinterpret_cast<const ulonglong2*>(hb[p]);
        unsigned long long acc2 = 0;
#pragma unroll
        for (int c = 0; c < 32; c++) {
            ulonglong2 hv = h2[c];   // broadcast LDS.128
            FMA2(acc2, w2[2 * c],     hv.x, acc2);
            FMA2(acc2, w2[2 * c + 1], hv.y, acc2);
        }
        float z = __uint_as_float((unsigned)acc2)
                + __uint_as_float((unsigned)(acc2 >> 32))
                + pre + bsum;
        // tanh(z) = 1 - 2/(exp(2z)+1); handles +/-inf of exp correctly.
        float e  = __expf(2.0f * z);
        float hn = 1.0f - __fdividef(2.0f, e + 1.0f);

        // Prefetch next step's symbol + pre before the barrier.
        t++;
        int sn = (t < Tt) ? (int)ssym[t] : 0;
        float pren = (sn > 0) ? g_WihT[(sn - 1) * Hh + tid] : 0.0f;

        hb[p ^ 1][tid] = hn;
        __syncthreads();
        p ^= 1;
        s = sn;
        pre = pren;
    }

    // Epilogue: h_last is in hb[p].
    float hv = hb[p][tid];
    out[2 * Bb + b * Hh + tid] = hv;               // hidden (1,B,H) at offset 512
    red[0][tid] = W_out[tid] * hv;                 // W_out row 0
    red[1][tid] = W_out[Hh + tid] * hv;            // W_out row 1
    __syncthreads();
    if (tid == 0) {
        float l0 = b_out[0], l1 = b_out[1];
#pragma unroll 8
        for (int i = 0; i < Hh; i++) { l0 += red[0][i]; l1 += red[1][i]; }
        float m  = fmaxf(l0, l1);
        float e0 = __expf(l0 - m), e1 = __expf(l1 - m);
        float inv = __fdividef(1.0f, e0 + e1);
        out[b * 2 + 0] = e0 * inv;                 // fed (B,2) at offset 0
        out[b * 2 + 1] = e1 * inv;
    }
}

// ---------------------------------------------------------------------------
extern "C" void kernel_launch(void* const* d_in, const int* in_sizes, int n_in,
                              void* d_out, int out_size) {
    (void)in_sizes; (void)n_in; (void)out_size;
    const float* x     = (const float*)d_in[0];
    const float* W_ih  = (const float*)d_in[1];
    const float* W_hh  = (const float*)d_in[2];
    const float* b_ih  = (const float*)d_in[3];
    const float* b_hh  = (const float*)d_in[4];
    const float* W_out = (const float*)d_in[5];
    const float* b_out = (const float*)d_in[6];
    float* out = (float*)d_out;

    sym_kernel<<<(Bb * Tt) / 8, 256>>>(x);
    transpose_kernel<<<127, 128>>>(W_ih);
    rnn_kernel<<<Bb, 128>>>(W_hh, b_ih, b_hh, W_out, b_out, out);
}